// round 15
// baseline (speedup 1.0000x reference)
#include <cuda_runtime.h>
#include <math.h>
#include <stdint.h>

// ---------------- problem constants ----------------
#define S 2048
#define HID 2048
#define NH 32
#define HD 64
#define Q_W 4096            // 2*HID
#define SCALE 0.125f        // 1/sqrt(64)
#define LAM_INIT 0.7836057665316245
#define NEG_BIG (-1e30f)

// ---------------- scratch (device globals, no allocation) ----------------
__device__ float    g_Q[(size_t)S * Q_W];     // tf32 bits (rope fused in gemm)
__device__ float    g_K[(size_t)S * Q_W];     // tf32 bits
__device__ float    g_V[(size_t)S * HID];     // tf32 bits
__device__ float    g_O1[(size_t)S * HID];    // fp32
__device__ float    g_O2[(size_t)S * HID];    // fp32
__device__ float    g_CTX[(size_t)S * HID];   // tf32 bits
__device__ unsigned g_Ht[(size_t)S * HID];    // hid in tf32 bits
__device__ unsigned g_Wqt[(size_t)Q_W * HID];
__device__ unsigned g_Wkt[(size_t)Q_W * HID];
__device__ unsigned g_Wvt[(size_t)HID * HID];
__device__ unsigned g_Wot[(size_t)HID * HID];
__device__ float g_cos[S * 32];
__device__ float g_sin[S * 32];
__device__ float g_lam;

// ---------------- tf32 helpers ----------------
__device__ __forceinline__ unsigned f2tf(float x) {
    unsigned r;
    asm("cvt.rna.tf32.f32 %0, %1;" : "=r"(r) : "f"(x));
    return r;
}
__device__ __forceinline__ void mma_tf32(float c[4],
                                         unsigned a0, unsigned a1, unsigned a2, unsigned a3,
                                         unsigned b0, unsigned b1) {
    asm volatile(
        "mma.sync.aligned.m16n8k8.row.col.f32.tf32.tf32.f32 "
        "{%0,%1,%2,%3},{%4,%5,%6,%7},{%8,%9},{%0,%1,%2,%3};"
        : "+f"(c[0]), "+f"(c[1]), "+f"(c[2]), "+f"(c[3])
        : "r"(a0), "r"(a1), "r"(a2), "r"(a3), "r"(b0), "r"(b1));
}

// ---------------- pre-convert fp32 -> tf32 bits ----------------
__global__ void cvt_tf32_kernel(const float4* __restrict__ in,
                                uint4* __restrict__ out, int n4) {
    int i = blockIdx.x * blockDim.x + threadIdx.x;
    if (i >= n4) return;
    float4 v = in[i];
    out[i] = make_uint4(f2tf(v.x), f2tf(v.y), f2tf(v.z), f2tf(v.w));
}

// ---------------- lambda scalar ----------------
__global__ void lam_kernel(const float* __restrict__ lq1, const float* __restrict__ lk1,
                           const float* __restrict__ lq2, const float* __restrict__ lk2) {
    if (threadIdx.x == 0) {
        float d1 = 0.f, d2 = 0.f;
        for (int i = 0; i < HD; i++) { d1 += lq1[i] * lk1[i]; d2 += lq2[i] * lk2[i]; }
        g_lam = expf(d1) - expf(d2) + (float)LAM_INIT;
    }
}

// ---------------- RoPE table (float64 like reference) ----------------
__global__ void rope_table_kernel() {
    int idx = blockIdx.x * blockDim.x + threadIdx.x;
    if (idx >= S * 32) return;
    int s = idx >> 5;
    int d = idx & 31;
    double inv = pow(10000.0, -(double)d / 32.0);
    double ang = (double)s * inv;
    g_cos[idx] = (float)cos(ang);
    g_sin[idx] = (float)sin(ang);
}

// ================= TF32 GEMM core (double-buffered, 1 sync/tile) ===========
// mode: 0 = fp32 out, 1 = tf32-bits out, 2 = fused RoPE + tf32-bits out.
// Mode-2 epilogue: acc -> staging smem, sync, re-read own+partner (acc dead
// across the barrier -> register pressure stays <=128 -> 2 CTAs/SM).
#define GA_STR 36
#define HALF_W (128 * GA_STR)                 // words per A (or B) buffer
#define STAGE_W (2 * HALF_W)                  // words per stage
#define GEMM_SMEM_BYTES (2 * STAGE_W * 4)     // 73728
#define ST_STR 130                            // rope staging stride (words)

__device__ __forceinline__ void gemm_fill(const unsigned* __restrict__ Ab,
                                          const unsigned* __restrict__ Bb,
                                          unsigned* stage, int K, int kc, int tid) {
    unsigned* As = stage;
    unsigned* Bs = stage + HALF_W;
#pragma unroll
    for (int i = 0; i < 4; i++) {
        int lin = i * 256 + tid, row = lin >> 3, q = lin & 7;
        uint4 va = *(const uint4*)(Ab + (size_t)row * K + kc * 32 + q * 4);
        uint4 vb = *(const uint4*)(Bb + (size_t)row * K + kc * 32 + q * 4);
        *(uint4*)&As[row * GA_STR + q * 4] = va;
        *(uint4*)&Bs[row * GA_STR + q * 4] = vb;
    }
}

__device__ __forceinline__ void gemm_body(const unsigned* __restrict__ Ab,
                                          const unsigned* __restrict__ Bb,
                                          float* __restrict__ Cb,
                                          int N, int K, int mode, int bm,
                                          unsigned* sm) {
    const int tid  = threadIdx.x;
    const int lane = tid & 31;
    const int warp = tid >> 5;
    const int wm = (warp >> 2) * 64;
    const int wn = (warp & 3) * 32;
    const int a  = lane >> 2;
    const int mm = lane & 3;

    float acc[4][4][4];
#pragma unroll
    for (int i = 0; i < 4; i++)
#pragma unroll
        for (int j = 0; j < 4; j++)
#pragma unroll
            for (int r = 0; r < 4; r++) acc[i][j][r] = 0.f;

    const int nk = K >> 5;
    gemm_fill(Ab, Bb, sm, K, 0, tid);
    __syncthreads();

    for (int kc = 0; kc < nk; kc++) {
        const int cur = kc & 1;
        if (kc + 1 < nk)
            gemm_fill(Ab, Bb, sm + (cur ^ 1) * STAGE_W, K, kc + 1, tid);

        const unsigned* As = sm + cur * STAGE_W;
        const unsigned* Bs = As + HALF_W;
#pragma unroll
        for (int k8 = 0; k8 < 4; k8++) {
            unsigned af[4][4], bf[4][2];
#pragma unroll
            for (int i = 0; i < 4; i++) {
                const unsigned* p  = &As[(wm + i * 16 + a) * GA_STR + k8 * 8 + mm];
                const unsigned* p2 = p + 8 * GA_STR;
                af[i][0] = p[0];  af[i][2] = p[4];
                af[i][1] = p2[0]; af[i][3] = p2[4];
            }
#pragma unroll
            for (int j = 0; j < 4; j++) {
                const unsigned* p = &Bs[(wn + j * 8 + a) * GA_STR + k8 * 8 + mm];
                bf[j][0] = p[0]; bf[j][1] = p[4];
            }
#pragma unroll
            for (int i = 0; i < 4; i++)
#pragma unroll
                for (int j = 0; j < 4; j++)
                    mma_tf32(acc[i][j], af[i][0], af[i][1], af[i][2], af[i][3],
                             bf[j][0], bf[j][1]);
        }
        __syncthreads();
    }

    if (mode == 2) {
        // ---- fused RoPE epilogue (register-safe): dump accs, reload both ----
        float* stg = (float*)sm;
#pragma unroll
        for (int i = 0; i < 4; i++) {
            int lr = wm + i * 16 + a;
            int lc = wn + mm * 2;
#pragma unroll
            for (int j = 0; j < 4; j++) {
                *(float2*)&stg[lr * ST_STR + lc + j * 8] =
                    make_float2(acc[i][j][0], acc[i][j][1]);
                *(float2*)&stg[(lr + 8) * ST_STR + lc + j * 8] =
                    make_float2(acc[i][j][2], acc[i][j][3]);
            }
        }
        __syncthreads();
        // acc is dead here; read own + partner from staging.
#pragma unroll
        for (int i = 0; i < 4; i++) {
#pragma unroll
            for (int rr = 0; rr < 2; rr++) {
                int lrow = wm + i * 16 + a + rr * 8;
                int sg = bm + lrow;
#pragma unroll
                for (int j = 0; j < 4; j++) {
                    int lc = wn + j * 8 + mm * 2;
                    float2 x = *(const float2*)&stg[lrow * ST_STR + lc];
                    float2 p = *(const float2*)&stg[lrow * ST_STR + (lc ^ 32)];
                    int d0  = lc & 63;
                    int d31 = d0 & 31;
                    float2 cs0 = *(const float2*)&g_cos[sg * 32 + d31];
                    float2 sn0 = *(const float2*)&g_sin[sg * 32 + d31];
                    float o0, o1;
                    if (d0 & 32) { o0 = x.x * cs0.x + p.x * sn0.x; o1 = x.y * cs0.y + p.y * sn0.y; }
                    else         { o0 = x.x * cs0.x - p.x * sn0.x; o1 = x.y * cs0.y - p.y * sn0.y; }
                    *(float2*)&Cb[(size_t)lrow * N + lc] = make_float2(
                        __uint_as_float(f2tf(o0)), __uint_as_float(f2tf(o1)));
                }
            }
        }
        return;
    }

#pragma unroll
    for (int i = 0; i < 4; i++) {
        int row = wm + i * 16 + a;
#pragma unroll
        for (int j = 0; j < 4; j++) {
            int col = wn + j * 8 + mm * 2;
            float v0 = acc[i][j][0], v1 = acc[i][j][1];
            float v2 = acc[i][j][2], v3 = acc[i][j][3];
            if (mode == 1) {
                v0 = __uint_as_float(f2tf(v0)); v1 = __uint_as_float(f2tf(v1));
                v2 = __uint_as_float(f2tf(v2)); v3 = __uint_as_float(f2tf(v3));
            }
            *(float2*)&Cb[(size_t)row * N + col]       = make_float2(v0, v1);
            *(float2*)&Cb[(size_t)(row + 8) * N + col] = make_float2(v2, v3);
        }
    }
}

// Fused Q/K/V projection: grid (80, 16). bx<32 -> Q(rope), <64 -> K(rope), else V.
__global__ __launch_bounds__(256, 2)
void gemm_qkv(const unsigned* __restrict__ Ht,
              const unsigned* __restrict__ Wqt, const unsigned* __restrict__ Wkt,
              const unsigned* __restrict__ Wvt,
              float* __restrict__ Qo, float* __restrict__ Ko, float* __restrict__ Vo) {
    extern __shared__ unsigned gsm[];
    const int bx = blockIdx.x;
    const int bm = blockIdx.y * 128;
    const unsigned* Bp; float* Cp; int N, mode, b;
    if (bx < 32)      { Bp = Wqt; Cp = Qo; N = Q_W; mode = 2; b = bx; }
    else if (bx < 64) { Bp = Wkt; Cp = Ko; N = Q_W; mode = 2; b = bx - 32; }
    else              { Bp = Wvt; Cp = Vo; N = HID; mode = 1; b = bx - 64; }
    gemm_body(Ht + (size_t)bm * HID, Bp + (size_t)b * 128 * HID,
              Cp + (size_t)bm * N + b * 128, N, HID, mode, bm, gsm);
}

// Output projection: grid (16, 16).
__global__ __launch_bounds__(256, 2)
void gemm_o(const unsigned* __restrict__ CTX, const unsigned* __restrict__ Wot,
            float* __restrict__ out) {
    extern __shared__ unsigned gsm[];
    const int bm = blockIdx.y * 128;
    const int bn = blockIdx.x * 128;
    gemm_body(CTX + (size_t)bm * HID, Wot + (size_t)bn * HID,
              out + (size_t)bm * HID + bn, HID, HID, 0, bm, gsm);
}

// ================= TF32 flash attention (Q-in-regs, K/V double-buffered) ===
#define KS_STR 68
#define VS_STR 72
#define PS_STR 68
#define KBUF_SZ (64 * KS_STR)                 // 4352
#define VBUF_OFF (2 * KBUF_SZ)                // 8704
#define VBUF_SZ (64 * VS_STR)                 // 4608
#define PS_OFF (VBUF_OFF + 2 * VBUF_SZ)       // 17920
#define FLASH_WORDS (PS_OFF + 128 * PS_STR)   // 26624
#define FLASH_BYTES (FLASH_WORDS * 4)         // 106496

__global__ __launch_bounds__(256, 2)
void flash_tf32(const unsigned* __restrict__ Qg, const unsigned* __restrict__ Kg,
                const unsigned* __restrict__ Vg,
                float* __restrict__ O1g, float* __restrict__ O2g) {
    extern __shared__ unsigned smw[];
    unsigned* Ps = smw + PS_OFF;

    const int tid  = threadIdx.x;
    const int lane = tid & 31;
    const int warp = tid >> 5;
    const int a  = lane >> 2;
    const int mm = lane & 3;
    const int qi = gridDim.x - 1 - blockIdx.x;   // heavy tiles first
    const int h  = blockIdx.y;
    const int st = blockIdx.z;
    const int coff = st * HID + h * HD;
    float* Og = st ? O2g : O1g;
    const int r0 = qi * 128;
    const int m0 = warp * 16;
    const int rA = m0 + a;

    // ---- stage Q into the K-buffer region, hoist fragments to registers ----
#pragma unroll
    for (int i = 0; i < 8; i++) {
        int lin = i * 256 + tid, row = lin >> 4, q = lin & 15;
        uint4 v = *(const uint4*)(Qg + (size_t)(r0 + row) * Q_W + coff + q * 4);
        *(uint4*)&smw[row * KS_STR + q * 4] = v;
    }
    __syncthreads();
    unsigned qf[8][4];
#pragma unroll
    for (int d8 = 0; d8 < 8; d8++) {
        qf[d8][0] = smw[rA * KS_STR + d8 * 8 + mm];
        qf[d8][2] = smw[rA * KS_STR + d8 * 8 + mm + 4];
        qf[d8][1] = smw[(rA + 8) * KS_STR + d8 * 8 + mm];
        qf[d8][3] = smw[(rA + 8) * KS_STR + d8 * 8 + mm + 4];
    }
    __syncthreads();   // Q staging reads done before K fill overwrites

    float oacc[8][4];
#pragma unroll
    for (int j = 0; j < 8; j++)
#pragma unroll
        for (int r = 0; r < 4; r++) oacc[j][r] = 0.f;
    float mr0 = NEG_BIG, mr1 = NEG_BIG, lr0 = 0.f, lr1 = 0.f;

    const int ktmax = 2 * qi + 1;

    // ---- prologue: fill buffer 0 with kv tile 0 ----
    {
        unsigned* Kb = smw;
        unsigned* Vb = smw + VBUF_OFF;
#pragma unroll
        for (int i = 0; i < 4; i++) {
            int lin = i * 256 + tid, row = lin >> 4, q = lin & 15;
            uint4 k = *(const uint4*)(Kg + (size_t)row * Q_W + coff + q * 4);
            uint4 v = *(const uint4*)(Vg + (size_t)row * HID + h * HD + q * 4);
            *(uint4*)&Kb[row * KS_STR + q * 4] = k;
            *(uint4*)&Vb[row * VS_STR + q * 4] = v;
        }
    }
    __syncthreads();

    for (int kt = 0; kt <= ktmax; kt++) {
        const int cur = kt & 1;
        const unsigned* Ks = smw + cur * KBUF_SZ;
        const unsigned* Vs = smw + VBUF_OFF + cur * VBUF_SZ;
        const int c0 = kt * 64;

        // prefetch next kv tile into the other buffers (overlaps mma below)
        if (kt < ktmax) {
            unsigned* Kn = smw + (cur ^ 1) * KBUF_SZ;
            unsigned* Vn = smw + VBUF_OFF + (cur ^ 1) * VBUF_SZ;
            const int c1 = c0 + 64;
#pragma unroll
            for (int i = 0; i < 4; i++) {
                int lin = i * 256 + tid, row = lin >> 4, q = lin & 15;
                uint4 k = *(const uint4*)(Kg + (size_t)(c1 + row) * Q_W + coff + q * 4);
                uint4 v = *(const uint4*)(Vg + (size_t)(c1 + row) * HID + h * HD + q * 4);
                *(uint4*)&Kn[row * KS_STR + q * 4] = k;
                *(uint4*)&Vn[row * VS_STR + q * 4] = v;
            }
        }

        // ---- S = Q K^T (Q from registers) ----
        float sacc[8][4];
#pragma unroll
        for (int j = 0; j < 8; j++)
#pragma unroll
            for (int r = 0; r < 4; r++) sacc[j][r] = 0.f;

#pragma unroll
        for (int d8 = 0; d8 < 8; d8++) {
#pragma unroll
            for (int j = 0; j < 8; j++) {
                unsigned b0 = Ks[(j * 8 + a) * KS_STR + d8 * 8 + mm];
                unsigned b1 = Ks[(j * 8 + a) * KS_STR + d8 * 8 + mm + 4];
                mma_tf32(sacc[j], qf[d8][0], qf[d8][1], qf[d8][2], qf[d8][3],
                         b0, b1);
            }
        }

        // ---- scale + causal mask ----
        bool dmask = (kt >= 2 * qi);
#pragma unroll
        for (int j = 0; j < 8; j++) {
#pragma unroll
            for (int r = 0; r < 4; r++) {
                float v = sacc[j][r] * SCALE;
                if (dmask) {
                    int gr = r0 + m0 + a + ((r >> 1) << 3);
                    int gc = c0 + j * 8 + mm * 2 + (r & 1);
                    if (gc > gr) v = NEG_BIG;
                }
                sacc[j][r] = v;
            }
        }

        // ---- online softmax (rows owned within 4-lane groups) ----
        float mx0 = NEG_BIG, mx1 = NEG_BIG;
#pragma unroll
        for (int j = 0; j < 8; j++) {
            mx0 = fmaxf(mx0, fmaxf(sacc[j][0], sacc[j][1]));
            mx1 = fmaxf(mx1, fmaxf(sacc[j][2], sacc[j][3]));
        }
        mx0 = fmaxf(mx0, __shfl_xor_sync(0xffffffffu, mx0, 1));
        mx0 = fmaxf(mx0, __shfl_xor_sync(0xffffffffu, mx0, 2));
        mx1 = fmaxf(mx1, __shfl_xor_sync(0xffffffffu, mx1, 1));
        mx1 = fmaxf(mx1, __shfl_xor_sync(0xffffffffu, mx1, 2));
        float mn0 = fmaxf(mr0, mx0), mn1 = fmaxf(mr1, mx1);
        float corr0 = __expf(mr0 - mn0), corr1 = __expf(mr1 - mn1);
        mr0 = mn0; mr1 = mn1;

        float ps0 = 0.f, ps1 = 0.f;
#pragma unroll
        for (int j = 0; j < 8; j++) {
            float p0 = __expf(sacc[j][0] - mn0);
            float p1 = __expf(sacc[j][1] - mn0);
            float p2 = __expf(sacc[j][2] - mn1);
            float p3 = __expf(sacc[j][3] - mn1);
            ps0 += p0 + p1; ps1 += p2 + p3;
            int col = j * 8 + mm * 2;
            Ps[rA * PS_STR + col]           = f2tf(p0);
            Ps[rA * PS_STR + col + 1]       = f2tf(p1);
            Ps[(rA + 8) * PS_STR + col]     = f2tf(p2);
            Ps[(rA + 8) * PS_STR + col + 1] = f2tf(p3);
        }
        ps0 += __shfl_xor_sync(0xffffffffu, ps0, 1);
        ps0 += __shfl_xor_sync(0xffffffffu, ps0, 2);
        ps1 += __shfl_xor_sync(0xffffffffu, ps1, 1);
        ps1 += __shfl_xor_sync(0xffffffffu, ps1, 2);
        lr0 = lr0 * corr0 + ps0;
        lr1 = lr1 * corr1 + ps1;
#pragma unroll
        for (int j = 0; j < 8; j++) {
            oacc[j][0] *= corr0; oacc[j][1] *= corr0;
            oacc[j][2] *= corr1; oacc[j][3] *= corr1;
        }
        __syncwarp();

        // ---- O += P V ----
#pragma unroll
        for (int kv8 = 0; kv8 < 8; kv8++) {
            unsigned a0 = Ps[rA * PS_STR + kv8 * 8 + mm];
            unsigned a2 = Ps[rA * PS_STR + kv8 * 8 + mm + 4];
            unsigned a1 = Ps[(rA + 8) * PS_STR + kv8 * 8 + mm];
            unsigned a3 = Ps[(rA + 8) * PS_STR + kv8 * 8 + mm + 4];
#pragma unroll
            for (int j = 0; j < 8; j++) {
                unsigned b0 = Vs[(kv8 * 8 + mm) * VS_STR + j * 8 + a];
                unsigned b1 = Vs[(kv8 * 8 + mm + 4) * VS_STR + j * 8 + a];
                mma_tf32(oacc[j], a0, a1, a2, a3, b0, b1);
            }
        }
        __syncthreads();
    }

    // ---- epilogue: normalize + write (fp32) ----
    float il0 = 1.f / lr0, il1 = 1.f / lr1;
#pragma unroll
    for (int j = 0; j < 8; j++) {
        int col = j * 8 + mm * 2;
        *(float2*)&Og[(size_t)(r0 + m0 + a) * HID + h * HD + col] =
            make_float2(oacc[j][0] * il0, oacc[j][1] * il0);
        *(float2*)&Og[(size_t)(r0 + m0 + a + 8) * HID + h * HD + col] =
            make_float2(oacc[j][2] * il1, oacc[j][3] * il1);
    }
}

// ---- combine: ctx = tf32(rmsnorm(o1 - lam*o2) * subln * (1-lam_init)) ----
__global__ __launch_bounds__(256)
void combine_kernel(const float* __restrict__ subln, float* __restrict__ ctx) {
    int warp = blockIdx.x * 8 + (threadIdx.x >> 5);
    int lane = threadIdx.x & 31;
    if (warp >= S * NH) return;
    int s = warp >> 5;
    int h = warp & 31;
    size_t base = (size_t)s * HID + h * HD + lane;
    float lam = g_lam;
    float c0 = g_O1[base]      - lam * g_O2[base];
    float c1 = g_O1[base + 32] - lam * g_O2[base + 32];
    float ss = c0 * c0 + c1 * c1;
#pragma unroll
    for (int o = 16; o >= 1; o >>= 1)
        ss += __shfl_xor_sync(0xffffffffu, ss, o);
    float inv = rsqrtf(ss * (1.f / 64.f) + 1e-6f);
    float sc  = inv * (1.f - (float)LAM_INIT);
    ctx[base]      = __uint_as_float(f2tf(c0 * sc * subln[lane]));
    ctx[base + 32] = __uint_as_float(f2tf(c1 * sc * subln[lane + 32]));
}

// ---------------- host launcher ----------------
extern "C" void kernel_launch(void* const* d_in, const int* in_sizes, int n_in,
                              void* d_out, int out_size) {
    const float* hid  = (const float*)d_in[0];
    const float* Wq   = (const float*)d_in[1];
    const float* Wk   = (const float*)d_in[2];
    const float* Wv   = (const float*)d_in[3];
    const float* Wo   = (const float*)d_in[4];
    const float* lq1  = (const float*)d_in[5];
    const float* lk1  = (const float*)d_in[6];
    const float* lq2  = (const float*)d_in[7];
    const float* lk2  = (const float*)d_in[8];
    const float* subw = (const float*)d_in[9];
    float* out = (float*)d_out;

    float *Q, *K, *V, *O1, *O2, *CTX;
    unsigned *Ht, *Wqt, *Wkt, *Wvt, *Wot;
    cudaGetSymbolAddress((void**)&Q,   g_Q);
    cudaGetSymbolAddress((void**)&K,   g_K);
    cudaGetSymbolAddress((void**)&V,   g_V);
    cudaGetSymbolAddress((void**)&O1,  g_O1);
    cudaGetSymbolAddress((void**)&O2,  g_O2);
    cudaGetSymbolAddress((void**)&CTX, g_CTX);
    cudaGetSymbolAddress((void**)&Ht,  g_Ht);
    cudaGetSymbolAddress((void**)&Wqt, g_Wqt);
    cudaGetSymbolAddress((void**)&Wkt, g_Wkt);
    cudaGetSymbolAddress((void**)&Wvt, g_Wvt);
    cudaGetSymbolAddress((void**)&Wot, g_Wot);

    cudaFuncSetAttribute(flash_tf32,
                         cudaFuncAttributeMaxDynamicSharedMemorySize, FLASH_BYTES);
    cudaFuncSetAttribute(gemm_qkv,
                         cudaFuncAttributeMaxDynamicSharedMemorySize, GEMM_SMEM_BYTES);
    cudaFuncSetAttribute(gemm_o,
                         cudaFuncAttributeMaxDynamicSharedMemorySize, GEMM_SMEM_BYTES);

    // lambda + rope table
    lam_kernel<<<1, 32>>>(lq1, lk1, lq2, lk2);
    rope_table_kernel<<<(S * 32 + 255) / 256, 256>>>();

    // pre-convert activations + weights to tf32 bits
    const int T = 256;
    int n4h = S * HID / 4, n4q = Q_W * HID / 4, n4v = HID * HID / 4;
    cvt_tf32_kernel<<<(n4h + T - 1) / T, T>>>((const float4*)hid, (uint4*)Ht,  n4h);
    cvt_tf32_kernel<<<(n4q + T - 1) / T, T>>>((const float4*)Wq,  (uint4*)Wqt, n4q);
    cvt_tf32_kernel<<<(n4q + T - 1) / T, T>>>((const float4*)Wk,  (uint4*)Wkt, n4q);
    cvt_tf32_kernel<<<(n4v + T - 1) / T, T>>>((const float4*)Wv,  (uint4*)Wvt, n4v);
    cvt_tf32_kernel<<<(n4v + T - 1) / T, T>>>((const float4*)Wo,  (uint4*)Wot, n4v);

    // fused Q/K/V projection with in-epilogue RoPE on Q and K
    gemm_qkv<<<dim3(80, S / 128), 256, GEMM_SMEM_BYTES>>>(Ht, Wqt, Wkt, Wvt, Q, K, V);

    // both differential-attention streams in one launch
    flash_tf32<<<dim3(S / 128, NH, 2), 256, FLASH_BYTES>>>(
        (const unsigned*)Q, (const unsigned*)K, (const unsigned*)V, O1, O2);

    // differential combine + headwise RMSNorm (writes tf32 bits)
    combine_kernel<<<(S * NH + 7) / 8, 256>>>(subw, CTX);

    // output projection
    gemm_o<<<dim3(HID / 128, S / 128), 256, GEMM_SMEM_BYTES>>>(
        (const unsigned*)CTX, Wot, out);
}

// round 16
// speedup vs baseline: 1.0407x; 1.0407x over previous
#include <cuda_runtime.h>
#include <math.h>
#include <stdint.h>

// ---------------- problem constants ----------------
#define S 2048
#define HID 2048
#define NH 32
#define HD 64
#define Q_W 4096            // 2*HID
#define SCALE 0.125f        // 1/sqrt(64)
#define LAM_INIT 0.7836057665316245
#define NEG_BIG (-1e30f)

// ---------------- scratch (device globals, no allocation) ----------------
__device__ float    g_Q[(size_t)S * Q_W];     // tf32 bits after rope
__device__ float    g_K[(size_t)S * Q_W];
__device__ float    g_V[(size_t)S * HID];     // tf32 bits (gemm epilogue converts)
__device__ float    g_O1[(size_t)S * HID];    // fp32
__device__ float    g_O2[(size_t)S * HID];    // fp32
__device__ float    g_CTX[(size_t)S * HID];   // tf32 bits (combine converts)
__device__ unsigned g_Ht[(size_t)S * HID];    // hid in tf32 bits
__device__ unsigned g_Wqt[(size_t)Q_W * HID];
__device__ unsigned g_Wkt[(size_t)Q_W * HID];
__device__ unsigned g_Wvt[(size_t)HID * HID];
__device__ unsigned g_Wot[(size_t)HID * HID];
__device__ float g_cos[S * 32];
__device__ float g_sin[S * 32];
__device__ float g_lam;

// ---------------- tf32 helpers ----------------
__device__ __forceinline__ unsigned f2tf(float x) {
    unsigned r;
    asm("cvt.rna.tf32.f32 %0, %1;" : "=r"(r) : "f"(x));
    return r;
}
__device__ __forceinline__ void mma_tf32(float c[4],
                                         unsigned a0, unsigned a1, unsigned a2, unsigned a3,
                                         unsigned b0, unsigned b1) {
    asm volatile(
        "mma.sync.aligned.m16n8k8.row.col.f32.tf32.tf32.f32 "
        "{%0,%1,%2,%3},{%4,%5,%6,%7},{%8,%9},{%0,%1,%2,%3};"
        : "+f"(c[0]), "+f"(c[1]), "+f"(c[2]), "+f"(c[3])
        : "r"(a0), "r"(a1), "r"(a2), "r"(a3), "r"(b0), "r"(b1));
}

// ---------------- merged pre-convert fp32 -> tf32 bits (one launch) --------
#define N4H (S * HID / 4)          // 1048576
#define N4Q (Q_W * HID / 4)        // 2097152
#define N4V (HID * HID / 4)        // 1048576
#define N4TOT (N4H + 2 * N4Q + 2 * N4V)

__global__ void cvt_all_kernel(const float4* __restrict__ hid,
                               const float4* __restrict__ wq,
                               const float4* __restrict__ wk,
                               const float4* __restrict__ wv,
                               const float4* __restrict__ wo,
                               uint4* __restrict__ ht,  uint4* __restrict__ wqt,
                               uint4* __restrict__ wkt, uint4* __restrict__ wvt,
                               uint4* __restrict__ wot) {
    int i = blockIdx.x * blockDim.x + threadIdx.x;
    if (i >= N4TOT) return;
    const float4* src; uint4* dst; int off;
    if (i < N4H)                         { src = hid; dst = ht;  off = i; }
    else if (i < N4H + N4Q)              { src = wq;  dst = wqt; off = i - N4H; }
    else if (i < N4H + 2 * N4Q)          { src = wk;  dst = wkt; off = i - N4H - N4Q; }
    else if (i < N4H + 2 * N4Q + N4V)    { src = wv;  dst = wvt; off = i - N4H - 2 * N4Q; }
    else                                 { src = wo;  dst = wot; off = i - N4H - 2 * N4Q - N4V; }
    float4 v = src[off];
    dst[off] = make_uint4(f2tf(v.x), f2tf(v.y), f2tf(v.z), f2tf(v.w));
}

// ---------------- lambda scalar ----------------
__global__ void lam_kernel(const float* __restrict__ lq1, const float* __restrict__ lk1,
                           const float* __restrict__ lq2, const float* __restrict__ lk2) {
    if (threadIdx.x == 0) {
        float d1 = 0.f, d2 = 0.f;
        for (int i = 0; i < HD; i++) { d1 += lq1[i] * lk1[i]; d2 += lq2[i] * lk2[i]; }
        g_lam = expf(d1) - expf(d2) + (float)LAM_INIT;
    }
}

// ---------------- RoPE table (float64 like reference) ----------------
__global__ void rope_table_kernel() {
    int idx = blockIdx.x * blockDim.x + threadIdx.x;
    if (idx >= S * 32) return;
    int s = idx >> 5;
    int d = idx & 31;
    double inv = pow(10000.0, -(double)d / 32.0);
    double ang = (double)s * inv;
    g_cos[idx] = (float)cos(ang);
    g_sin[idx] = (float)sin(ang);
}

// ---------------- RoPE in-place on [S, 4096]; writes tf32 bits ----------------
__global__ void rope_apply_kernel(float* __restrict__ X) {
    int idx = blockIdx.x * blockDim.x + threadIdx.x;   // S*2048 pairs
    if (idx >= S * 2048) return;
    int s    = idx >> 11;
    int p    = idx & 2047;
    int half = p >> 10;
    int rem  = p & 1023;
    int h    = rem >> 5;
    int d    = rem & 31;
    size_t base = (size_t)s * Q_W + half * HID + h * HD + d;
    float x1 = X[base];
    float x2 = X[base + 32];
    float c  = g_cos[s * 32 + d];
    float sn = g_sin[s * 32 + d];
    X[base]      = __uint_as_float(f2tf(x1 * c - x2 * sn));
    X[base + 32] = __uint_as_float(f2tf(x2 * c + x1 * sn));
}

// ================= TF32 GEMM core (R11/R14: double-buffered, 1 sync/tile) ==
#define GA_STR 36
#define HALF_W (128 * GA_STR)                 // words per A (or B) buffer
#define STAGE_W (2 * HALF_W)                  // words per stage
#define GEMM_SMEM_BYTES (2 * STAGE_W * 4)     // 73728

__device__ __forceinline__ void gemm_fill(const unsigned* __restrict__ Ab,
                                          const unsigned* __restrict__ Bb,
                                          unsigned* stage, int K, int kc, int tid) {
    unsigned* As = stage;
    unsigned* Bs = stage + HALF_W;
#pragma unroll
    for (int i = 0; i < 4; i++) {
        int lin = i * 256 + tid, row = lin >> 3, q = lin & 7;
        uint4 va = *(const uint4*)(Ab + (size_t)row * K + kc * 32 + q * 4);
        uint4 vb = *(const uint4*)(Bb + (size_t)row * K + kc * 32 + q * 4);
        *(uint4*)&As[row * GA_STR + q * 4] = va;
        *(uint4*)&Bs[row * GA_STR + q * 4] = vb;
    }
}

__device__ __forceinline__ void gemm_body(const unsigned* __restrict__ Ab,
                                          const unsigned* __restrict__ Bb,
                                          float* __restrict__ Cb,
                                          int N, int K, int cvt_out,
                                          unsigned* sm) {
    const int tid  = threadIdx.x;
    const int lane = tid & 31;
    const int warp = tid >> 5;
    const int wm = (warp >> 2) * 64;
    const int wn = (warp & 3) * 32;
    const int a  = lane >> 2;
    const int mm = lane & 3;

    float acc[4][4][4];
#pragma unroll
    for (int i = 0; i < 4; i++)
#pragma unroll
        for (int j = 0; j < 4; j++)
#pragma unroll
            for (int r = 0; r < 4; r++) acc[i][j][r] = 0.f;

    const int nk = K >> 5;
    gemm_fill(Ab, Bb, sm, K, 0, tid);
    __syncthreads();

    for (int kc = 0; kc < nk; kc++) {
        const int cur = kc & 1;
        if (kc + 1 < nk)
            gemm_fill(Ab, Bb, sm + (cur ^ 1) * STAGE_W, K, kc + 1, tid);

        const unsigned* As = sm + cur * STAGE_W;
        const unsigned* Bs = As + HALF_W;
#pragma unroll
        for (int k8 = 0; k8 < 4; k8++) {
            unsigned af[4][4], bf[4][2];
#pragma unroll
            for (int i = 0; i < 4; i++) {
                const unsigned* p  = &As[(wm + i * 16 + a) * GA_STR + k8 * 8 + mm];
                const unsigned* p2 = p + 8 * GA_STR;
                af[i][0] = p[0];  af[i][2] = p[4];
                af[i][1] = p2[0]; af[i][3] = p2[4];
            }
#pragma unroll
            for (int j = 0; j < 4; j++) {
                const unsigned* p = &Bs[(wn + j * 8 + a) * GA_STR + k8 * 8 + mm];
                bf[j][0] = p[0]; bf[j][1] = p[4];
            }
#pragma unroll
            for (int i = 0; i < 4; i++)
#pragma unroll
                for (int j = 0; j < 4; j++)
                    mma_tf32(acc[i][j], af[i][0], af[i][1], af[i][2], af[i][3],
                             bf[j][0], bf[j][1]);
        }
        __syncthreads();
    }

#pragma unroll
    for (int i = 0; i < 4; i++) {
        int row = wm + i * 16 + a;
#pragma unroll
        for (int j = 0; j < 4; j++) {
            int col = wn + j * 8 + mm * 2;
            float v0 = acc[i][j][0], v1 = acc[i][j][1];
            float v2 = acc[i][j][2], v3 = acc[i][j][3];
            if (cvt_out) {
                v0 = __uint_as_float(f2tf(v0)); v1 = __uint_as_float(f2tf(v1));
                v2 = __uint_as_float(f2tf(v2)); v3 = __uint_as_float(f2tf(v3));
            }
            *(float2*)&Cb[(size_t)row * N + col]       = make_float2(v0, v1);
            *(float2*)&Cb[(size_t)(row + 8) * N + col] = make_float2(v2, v3);
        }
    }
}

// Fused Q/K/V projection: grid (16 bm, 80 strips) -- bm fastest so all 16 bm
// are co-resident => Ht stays L2-resident and only ~19 weight strips are live
// at once (L2-friendly rasterization).
__global__ __launch_bounds__(256, 2)
void gemm_qkv(const unsigned* __restrict__ Ht,
              const unsigned* __restrict__ Wqt, const unsigned* __restrict__ Wkt,
              const unsigned* __restrict__ Wvt,
              float* __restrict__ Qo, float* __restrict__ Ko, float* __restrict__ Vo) {
    extern __shared__ unsigned gsm[];
    const int bx = blockIdx.y;          // strip id (0..79)
    const int bm = blockIdx.x * 128;    // bm fastest
    const unsigned* Bp; float* Cp; int N, cvt, b;
    if (bx < 32)      { Bp = Wqt; Cp = Qo; N = Q_W; cvt = 0; b = bx; }
    else if (bx < 64) { Bp = Wkt; Cp = Ko; N = Q_W; cvt = 0; b = bx - 32; }
    else              { Bp = Wvt; Cp = Vo; N = HID; cvt = 1; b = bx - 64; }
    gemm_body(Ht + (size_t)bm * HID, Bp + (size_t)b * 128 * HID,
              Cp + (size_t)bm * N + b * 128, N, HID, cvt, gsm);
}

// Output projection: grid (16, 16).
__global__ __launch_bounds__(256, 2)
void gemm_o(const unsigned* __restrict__ CTX, const unsigned* __restrict__ Wot,
            float* __restrict__ out) {
    extern __shared__ unsigned gsm[];
    const int bm = blockIdx.y * 128;
    const int bn = blockIdx.x * 128;
    gemm_body(CTX + (size_t)bm * HID, Wot + (size_t)bn * HID,
              out + (size_t)bm * HID + bn, HID, HID, 0, gsm);
}

// ================= TF32 flash attention (Q-in-regs, K/V double-buffered) ===
#define KS_STR 68
#define VS_STR 72
#define PS_STR 68
#define KBUF_SZ (64 * KS_STR)                 // 4352
#define VBUF_OFF (2 * KBUF_SZ)                // 8704
#define VBUF_SZ (64 * VS_STR)                 // 4608
#define PS_OFF (VBUF_OFF + 2 * VBUF_SZ)       // 17920
#define FLASH_WORDS (PS_OFF + 128 * PS_STR)   // 26624
#define FLASH_BYTES (FLASH_WORDS * 4)         // 106496

__global__ __launch_bounds__(256, 2)
void flash_tf32(const unsigned* __restrict__ Qg, const unsigned* __restrict__ Kg,
                const unsigned* __restrict__ Vg,
                float* __restrict__ O1g, float* __restrict__ O2g) {
    extern __shared__ unsigned smw[];
    unsigned* Ps = smw + PS_OFF;

    const int tid  = threadIdx.x;
    const int lane = tid & 31;
    const int warp = tid >> 5;
    const int a  = lane >> 2;
    const int mm = lane & 3;
    const int qi = gridDim.x - 1 - blockIdx.x;   // heavy tiles first
    const int h  = blockIdx.y;
    const int st = blockIdx.z;
    const int coff = st * HID + h * HD;
    float* Og = st ? O2g : O1g;
    const int r0 = qi * 128;
    const int m0 = warp * 16;
    const int rA = m0 + a;

    // ---- stage Q into the K-buffer region, hoist fragments to registers ----
#pragma unroll
    for (int i = 0; i < 8; i++) {
        int lin = i * 256 + tid, row = lin >> 4, q = lin & 15;
        uint4 v = *(const uint4*)(Qg + (size_t)(r0 + row) * Q_W + coff + q * 4);
        *(uint4*)&smw[row * KS_STR + q * 4] = v;
    }
    __syncthreads();
    unsigned qf[8][4];
#pragma unroll
    for (int d8 = 0; d8 < 8; d8++) {
        qf[d8][0] = smw[rA * KS_STR + d8 * 8 + mm];
        qf[d8][2] = smw[rA * KS_STR + d8 * 8 + mm + 4];
        qf[d8][1] = smw[(rA + 8) * KS_STR + d8 * 8 + mm];
        qf[d8][3] = smw[(rA + 8) * KS_STR + d8 * 8 + mm + 4];
    }
    __syncthreads();   // Q staging reads done before K fill overwrites

    float oacc[8][4];
#pragma unroll
    for (int j = 0; j < 8; j++)
#pragma unroll
        for (int r = 0; r < 4; r++) oacc[j][r] = 0.f;
    float mr0 = NEG_BIG, mr1 = NEG_BIG, lr0 = 0.f, lr1 = 0.f;

    const int ktmax = 2 * qi + 1;

    // ---- prologue: fill buffer 0 with kv tile 0 ----
    {
        unsigned* Kb = smw;
        unsigned* Vb = smw + VBUF_OFF;
#pragma unroll
        for (int i = 0; i < 4; i++) {
            int lin = i * 256 + tid, row = lin >> 4, q = lin & 15;
            uint4 k = *(const uint4*)(Kg + (size_t)row * Q_W + coff + q * 4);
            uint4 v = *(const uint4*)(Vg + (size_t)row * HID + h * HD + q * 4);
            *(uint4*)&Kb[row * KS_STR + q * 4] = k;
            *(uint4*)&Vb[row * VS_STR + q * 4] = v;
        }
    }
    __syncthreads();

    for (int kt = 0; kt <= ktmax; kt++) {
        const int cur = kt & 1;
        const unsigned* Ks = smw + cur * KBUF_SZ;
        const unsigned* Vs = smw + VBUF_OFF + cur * VBUF_SZ;
        const int c0 = kt * 64;

        // prefetch next kv tile into the other buffers (overlaps mma below)
        if (kt < ktmax) {
            unsigned* Kn = smw + (cur ^ 1) * KBUF_SZ;
            unsigned* Vn = smw + VBUF_OFF + (cur ^ 1) * VBUF_SZ;
            const int c1 = c0 + 64;
#pragma unroll
            for (int i = 0; i < 4; i++) {
                int lin = i * 256 + tid, row = lin >> 4, q = lin & 15;
                uint4 k = *(const uint4*)(Kg + (size_t)(c1 + row) * Q_W + coff + q * 4);
                uint4 v = *(const uint4*)(Vg + (size_t)(c1 + row) * HID + h * HD + q * 4);
                *(uint4*)&Kn[row * KS_STR + q * 4] = k;
                *(uint4*)&Vn[row * VS_STR + q * 4] = v;
            }
        }

        // ---- S = Q K^T (Q from registers) ----
        float sacc[8][4];
#pragma unroll
        for (int j = 0; j < 8; j++)
#pragma unroll
            for (int r = 0; r < 4; r++) sacc[j][r] = 0.f;

#pragma unroll
        for (int d8 = 0; d8 < 8; d8++) {
#pragma unroll
            for (int j = 0; j < 8; j++) {
                unsigned b0 = Ks[(j * 8 + a) * KS_STR + d8 * 8 + mm];
                unsigned b1 = Ks[(j * 8 + a) * KS_STR + d8 * 8 + mm + 4];
                mma_tf32(sacc[j], qf[d8][0], qf[d8][1], qf[d8][2], qf[d8][3],
                         b0, b1);
            }
        }

        // ---- scale + causal mask ----
        bool dmask = (kt >= 2 * qi);
#pragma unroll
        for (int j = 0; j < 8; j++) {
#pragma unroll
            for (int r = 0; r < 4; r++) {
                float v = sacc[j][r] * SCALE;
                if (dmask) {
                    int gr = r0 + m0 + a + ((r >> 1) << 3);
                    int gc = c0 + j * 8 + mm * 2 + (r & 1);
                    if (gc > gr) v = NEG_BIG;
                }
                sacc[j][r] = v;
            }
        }

        // ---- online softmax (rows owned within 4-lane groups) ----
        float mx0 = NEG_BIG, mx1 = NEG_BIG;
#pragma unroll
        for (int j = 0; j < 8; j++) {
            mx0 = fmaxf(mx0, fmaxf(sacc[j][0], sacc[j][1]));
            mx1 = fmaxf(mx1, fmaxf(sacc[j][2], sacc[j][3]));
        }
        mx0 = fmaxf(mx0, __shfl_xor_sync(0xffffffffu, mx0, 1));
        mx0 = fmaxf(mx0, __shfl_xor_sync(0xffffffffu, mx0, 2));
        mx1 = fmaxf(mx1, __shfl_xor_sync(0xffffffffu, mx1, 1));
        mx1 = fmaxf(mx1, __shfl_xor_sync(0xffffffffu, mx1, 2));
        float mn0 = fmaxf(mr0, mx0), mn1 = fmaxf(mr1, mx1);
        float corr0 = __expf(mr0 - mn0), corr1 = __expf(mr1 - mn1);
        mr0 = mn0; mr1 = mn1;

        float ps0 = 0.f, ps1 = 0.f;
#pragma unroll
        for (int j = 0; j < 8; j++) {
            float p0 = __expf(sacc[j][0] - mn0);
            float p1 = __expf(sacc[j][1] - mn0);
            float p2 = __expf(sacc[j][2] - mn1);
            float p3 = __expf(sacc[j][3] - mn1);
            ps0 += p0 + p1; ps1 += p2 + p3;
            int col = j * 8 + mm * 2;
            Ps[rA * PS_STR + col]           = f2tf(p0);
            Ps[rA * PS_STR + col + 1]       = f2tf(p1);
            Ps[(rA + 8) * PS_STR + col]     = f2tf(p2);
            Ps[(rA + 8) * PS_STR + col + 1] = f2tf(p3);
        }
        ps0 += __shfl_xor_sync(0xffffffffu, ps0, 1);
        ps0 += __shfl_xor_sync(0xffffffffu, ps0, 2);
        ps1 += __shfl_xor_sync(0xffffffffu, ps1, 1);
        ps1 += __shfl_xor_sync(0xffffffffu, ps1, 2);
        lr0 = lr0 * corr0 + ps0;
        lr1 = lr1 * corr1 + ps1;
#pragma unroll
        for (int j = 0; j < 8; j++) {
            oacc[j][0] *= corr0; oacc[j][1] *= corr0;
            oacc[j][2] *= corr1; oacc[j][3] *= corr1;
        }
        __syncwarp();

        // ---- O += P V ----
#pragma unroll
        for (int kv8 = 0; kv8 < 8; kv8++) {
            unsigned a0 = Ps[rA * PS_STR + kv8 * 8 + mm];
            unsigned a2 = Ps[rA * PS_STR + kv8 * 8 + mm + 4];
            unsigned a1 = Ps[(rA + 8) * PS_STR + kv8 * 8 + mm];
            unsigned a3 = Ps[(rA + 8) * PS_STR + kv8 * 8 + mm + 4];
#pragma unroll
            for (int j = 0; j < 8; j++) {
                unsigned b0 = Vs[(kv8 * 8 + mm) * VS_STR + j * 8 + a];
                unsigned b1 = Vs[(kv8 * 8 + mm + 4) * VS_STR + j * 8 + a];
                mma_tf32(oacc[j], a0, a1, a2, a3, b0, b1);
            }
        }
        __syncthreads();
    }

    // ---- epilogue: normalize + write (fp32) ----
    float il0 = 1.f / lr0, il1 = 1.f / lr1;
#pragma unroll
    for (int j = 0; j < 8; j++) {
        int col = j * 8 + mm * 2;
        *(float2*)&Og[(size_t)(r0 + m0 + a) * HID + h * HD + col] =
            make_float2(oacc[j][0] * il0, oacc[j][1] * il0);
        *(float2*)&Og[(size_t)(r0 + m0 + a + 8) * HID + h * HD + col] =
            make_float2(oacc[j][2] * il1, oacc[j][3] * il1);
    }
}

// ---- combine: ctx = tf32(rmsnorm(o1 - lam*o2) * subln * (1-lam_init)) ----
__global__ __launch_bounds__(256)
void combine_kernel(const float* __restrict__ subln, float* __restrict__ ctx) {
    int warp = blockIdx.x * 8 + (threadIdx.x >> 5);
    int lane = threadIdx.x & 31;
    if (warp >= S * NH) return;
    int s = warp >> 5;
    int h = warp & 31;
    size_t base = (size_t)s * HID + h * HD + lane;
    float lam = g_lam;
    float c0 = g_O1[base]      - lam * g_O2[base];
    float c1 = g_O1[base + 32] - lam * g_O2[base + 32];
    float ss = c0 * c0 + c1 * c1;
#pragma unroll
    for (int o = 16; o >= 1; o >>= 1)
        ss += __shfl_xor_sync(0xffffffffu, ss, o);
    float inv = rsqrtf(ss * (1.f / 64.f) + 1e-6f);
    float sc  = inv * (1.f - (float)LAM_INIT);
    ctx[base]      = __uint_as_float(f2tf(c0 * sc * subln[lane]));
    ctx[base + 32] = __uint_as_float(f2tf(c1 * sc * subln[lane + 32]));
}

// ---------------- host launcher ----------------
extern "C" void kernel_launch(void* const* d_in, const int* in_sizes, int n_in,
                              void* d_out, int out_size) {
    const float* hid  = (const float*)d_in[0];
    const float* Wq   = (const float*)d_in[1];
    const float* Wk   = (const float*)d_in[2];
    const float* Wv   = (const float*)d_in[3];
    const float* Wo   = (const float*)d_in[4];
    const float* lq1  = (const float*)d_in[5];
    const float* lk1  = (const float*)d_in[6];
    const float* lq2  = (const float*)d_in[7];
    const float* lk2  = (const float*)d_in[8];
    const float* subw = (const float*)d_in[9];
    float* out = (float*)d_out;

    float *Q, *K, *V, *O1, *O2, *CTX;
    unsigned *Ht, *Wqt, *Wkt, *Wvt, *Wot;
    cudaGetSymbolAddress((void**)&Q,   g_Q);
    cudaGetSymbolAddress((void**)&K,   g_K);
    cudaGetSymbolAddress((void**)&V,   g_V);
    cudaGetSymbolAddress((void**)&O1,  g_O1);
    cudaGetSymbolAddress((void**)&O2,  g_O2);
    cudaGetSymbolAddress((void**)&CTX, g_CTX);
    cudaGetSymbolAddress((void**)&Ht,  g_Ht);
    cudaGetSymbolAddress((void**)&Wqt, g_Wqt);
    cudaGetSymbolAddress((void**)&Wkt, g_Wkt);
    cudaGetSymbolAddress((void**)&Wvt, g_Wvt);
    cudaGetSymbolAddress((void**)&Wot, g_Wot);

    cudaFuncSetAttribute(flash_tf32,
                         cudaFuncAttributeMaxDynamicSharedMemorySize, FLASH_BYTES);
    cudaFuncSetAttribute(gemm_qkv,
                         cudaFuncAttributeMaxDynamicSharedMemorySize, GEMM_SMEM_BYTES);
    cudaFuncSetAttribute(gemm_o,
                         cudaFuncAttributeMaxDynamicSharedMemorySize, GEMM_SMEM_BYTES);

    // lambda + rope table
    lam_kernel<<<1, 32>>>(lq1, lk1, lq2, lk2);
    rope_table_kernel<<<(S * 32 + 255) / 256, 256>>>();

    // merged pre-convert (one launch for hid + 4 weights)
    cvt_all_kernel<<<(N4TOT + 255) / 256, 256>>>(
        (const float4*)hid, (const float4*)Wq, (const float4*)Wk,
        (const float4*)Wv, (const float4*)Wo,
        (uint4*)Ht, (uint4*)Wqt, (uint4*)Wkt, (uint4*)Wvt, (uint4*)Wot);

    // fused Q/K/V projection (bm-fastest rasterization for L2 reuse)
    gemm_qkv<<<dim3(S / 128, 80), 256, GEMM_SMEM_BYTES>>>(Ht, Wqt, Wkt, Wvt, Q, K, V);

    // RoPE on Q and K (fp32 math, writes tf32 bits)
    rope_apply_kernel<<<(S * 2048 + 255) / 256, 256>>>(Q);
    rope_apply_kernel<<<(S * 2048 + 255) / 256, 256>>>(K);

    // both differential-attention streams in one launch
    flash_tf32<<<dim3(S / 128, NH, 2), 256, FLASH_BYTES>>>(
        (const unsigned*)Q, (const unsigned*)K, (const unsigned*)V, O1, O2);

    // differential combine + headwise RMSNorm (writes tf32 bits)
    combine_kernel<<<(S * NH + 7) / 8, 256>>>(subw, CTX);

    // output projection
    gemm_o<<<dim3(HID / 128, S / 128), 256, GEMM_SMEM_BYTES>>>(
        (const unsigned*)CTX, Wot, out);
}